// round 16
// baseline (speedup 1.0000x reference)
#include <cuda_runtime.h>
#include <cuda_fp16.h>
#include <stdint.h>

#define S_LEN 2048
#define DH    128
#define BH    64
#define NT    128            // 4 warps; 3 CTAs co-resident per SM
#define QT_ROWS 64
#define KT_ROWS 64

#define ELEMS ((size_t)BH * S_LEN * DH)
#define QUADS (ELEMS / 4)

__device__ __align__(16) __half g_kh[ELEMS];
__device__ __align__(16) __half g_vh[ELEMS];

// SMEM: two 32KB stages {Kh,Vh}; Q staged through stage0 in the prologue
#define STAGE_B 32768u
#define OFF_VH  16384u
#define SM_TOTAL 65536

// scale * log2(e): exp(s) = ex2(q'.k) with q' = q * scale * log2e
#define SCALE_L2E 0.12751791802533652f

__device__ __forceinline__ uint32_t pack2h(float x, float y) {
    __half2 h = __floats2half2_rn(x, y);
    return *(uint32_t*)&h;
}
__device__ __forceinline__ float ex2f(float x) {
    float y;
    asm("ex2.approx.f32 %0, %1;" : "=f"(y) : "f"(x));
    return y;
}

__global__ void split_prep(const float* __restrict__ K, const float* __restrict__ V)
{
    const float4* k4 = (const float4*)K;
    const float4* v4 = (const float4*)V;
    uint2* kh = (uint2*)g_kh;
    uint2* vh = (uint2*)g_vh;
    size_t i = (size_t)blockIdx.x * blockDim.x + threadIdx.x;   // exact fit, no loop
    if (i < QUADS) {
        float4 k = k4[i];
        kh[i] = make_uint2(pack2h(k.x, k.y), pack2h(k.z, k.w));
        float4 v = v4[i];
        vh[i] = make_uint2(pack2h(v.x, v.y), pack2h(v.z, v.w));
    }
}

__device__ __forceinline__ uint32_t smem_u32(const void* p) {
    uint32_t a;
    asm("{ .reg .u64 t; cvta.to.shared.u64 t, %1; cvt.u32.u64 %0, t; }" : "=r"(a) : "l"(p));
    return a;
}
__device__ __forceinline__ void cpa16(uint32_t dst, const void* src) {
    asm volatile("cp.async.cg.shared.global [%0], [%1], 16;" :: "r"(dst), "l"(src));
}
#define CP_COMMIT() asm volatile("cp.async.commit_group;" ::: "memory")
#define CP_WAIT1()  asm volatile("cp.async.wait_group 1;" ::: "memory")
#define CP_WAIT0()  asm volatile("cp.async.wait_group 0;" ::: "memory")

#define LDSM_X4(r0,r1,r2,r3,a) \
    asm volatile("ldmatrix.sync.aligned.m8n8.x4.shared.b16 {%0,%1,%2,%3},[%4];" \
                 : "=r"(r0),"=r"(r1),"=r"(r2),"=r"(r3) : "r"(a))
#define LDSM_X4T(r0,r1,r2,r3,a) \
    asm volatile("ldmatrix.sync.aligned.m8n8.x4.trans.shared.b16 {%0,%1,%2,%3},[%4];" \
                 : "=r"(r0),"=r"(r1),"=r"(r2),"=r"(r3) : "r"(a))
#define MMA(c,a0,a1,a2,a3,b0,b1) \
    asm volatile("mma.sync.aligned.m16n8k16.row.col.f32.f16.f16.f32 " \
                 "{%0,%1,%2,%3},{%4,%5,%6,%7},{%8,%9},{%0,%1,%2,%3};" \
                 : "+f"((c)[0]),"+f"((c)[1]),"+f"((c)[2]),"+f"((c)[3]) \
                 : "r"(a0),"r"(a1),"r"(a2),"r"(a3),"r"(b0),"r"(b1))

__global__ __launch_bounds__(NT, 3)
void fa_mma_kernel(const float* __restrict__ Qg_all, float* __restrict__ Og)
{
    extern __shared__ __align__(16) char sm8[];
    const uint32_t smb = smem_u32(sm8);
    const int tid = threadIdx.x;
    const int w = tid >> 5, l = tid & 31;

    const int qt = (int)gridDim.x - 1 - (int)blockIdx.x;   // heaviest first
    const int bh = blockIdx.y;
    const size_t gbase = (size_t)bh * S_LEN * DH;
    const int ntk = qt + 1;

    const int aswz = l & 7;
    const int ainc = l >> 4;

    // ---- Q prologue: convert into stage0 smem, ldmatrix to persistent regs ----
    uint32_t qf[32];                 // 8 ks-steps x 4 regs; Q pre-scaled by scale*log2e
    {
        const float4* q4 = (const float4*)(Qg_all + gbase + (size_t)qt * QT_ROWS * DH);
        #pragma unroll
        for (int i = 0; i < 8; i++) {
            int it  = tid + i * NT;          // 64 rows x 16 chunks
            int row = it >> 4, ch = it & 15;
            float4 f0 = q4[row * 32 + ch * 2];
            float4 f1 = q4[row * 32 + ch * 2 + 1];
            uint4 hq = make_uint4(pack2h(f0.x*SCALE_L2E, f0.y*SCALE_L2E),
                                  pack2h(f0.z*SCALE_L2E, f0.w*SCALE_L2E),
                                  pack2h(f1.x*SCALE_L2E, f1.y*SCALE_L2E),
                                  pack2h(f1.z*SCALE_L2E, f1.w*SCALE_L2E));
            *(uint4*)(sm8 + (row << 8) + ((ch ^ (row & 7)) << 4)) = hq;
        }
        __syncthreads();
        const uint32_t qrowaddr = smb + (uint32_t)((16 * w + (l & 15)) << 8);
        #pragma unroll
        for (int ks = 0; ks < 8; ks++) {
            uint32_t qa = qrowaddr + (uint32_t)(((2*ks + ainc) ^ aswz) << 4);
            LDSM_X4(qf[4*ks], qf[4*ks+1], qf[4*ks+2], qf[4*ks+3], qa);
        }
        __syncthreads();             // stage0 free for K/V
    }

    auto load_kv = [&](int buf, int kti) {
        const uint32_t st = smb + (uint32_t)buf * STAGE_B;
        const size_t gb = gbase + (size_t)kti * KT_ROWS * DH;
        #pragma unroll
        for (int i = 0; i < 16; i++) {
            int it  = tid + i * NT;          // 2 arrays x 64 rows x 16 chunks
            int arr = it >> 10;
            int row = (it >> 4) & 63;
            int ch  = it & 15;
            uint32_t dst = st + (uint32_t)arr * 16384u + (row << 8) + ((ch ^ (row & 7)) << 4);
            const __half* sp = (arr == 0) ? g_kh : g_vh;
            cpa16(dst, sp + gb + (size_t)row * DH + ch * 8);
        }
    };
    load_kv(0, 0);
    CP_COMMIT();
    if (ntk > 1) { load_kv(1, 1); }
    CP_COMMIT();                     // may be empty; keeps wait counts uniform
    CP_WAIT1();                      // tile 0 resident
    __syncthreads();                 // visible to all warps

    float Oa[16][4];
    #pragma unroll
    for (int i = 0; i < 16; i++) { Oa[i][0]=Oa[i][1]=Oa[i][2]=Oa[i][3]=0.f; }
    float lsum0 = 0.f, lsum1 = 0.f;

    const int grow0  = qt * QT_ROWS + 16 * w + (l >> 2);
    const int rowmax = qt * QT_ROWS + 16 * w + 15;

    for (int kt = 0; kt < ntk; kt++) {
        const int kbase = kt * KT_ROWS;
        {
            const uint32_t st  = smb + (uint32_t)(kt & 1) * STAGE_B;
            const uint32_t sKH = st, sVH = st + OFF_VH;
            const bool wfull = (kbase + KT_ROWS - 1) <= (qt * QT_ROWS + 16 * w);

            #pragma unroll
            for (int half = 0; half < 2; half++) {
                if (kbase + 32 * half > rowmax) break;   // skip masked half-tiles

                // ---- S' = Q' @ K^T over 32 k-cols (log2-domain) ----
                float Sa[4][4];
                #pragma unroll
                for (int i = 0; i < 4; i++) { Sa[i][0]=Sa[i][1]=Sa[i][2]=Sa[i][3]=0.f; }

                #pragma unroll
                for (int ks = 0; ks < 8; ks++) {
                    uint32_t kh[8];
                    #pragma unroll
                    for (int pp = 0; pp < 2; pp++) {
                        int p = 2*half + pp;
                        uint32_t ka = sKH + (uint32_t)((8*(2*p + (l>>4)) + (l & 7)) << 8)
                                          + (uint32_t)(((2*ks + ((l>>3)&1)) ^ aswz) << 4);
                        LDSM_X4(kh[4*pp],kh[4*pp+1],kh[4*pp+2],kh[4*pp+3], ka);
                    }
                    MMA(Sa[0], qf[4*ks],qf[4*ks+1],qf[4*ks+2],qf[4*ks+3], kh[0],kh[1]);
                    MMA(Sa[1], qf[4*ks],qf[4*ks+1],qf[4*ks+2],qf[4*ks+3], kh[2],kh[3]);
                    MMA(Sa[2], qf[4*ks],qf[4*ks+1],qf[4*ks+2],qf[4*ks+3], kh[4],kh[5]);
                    MMA(Sa[3], qf[4*ks],qf[4*ks+1],qf[4*ks+2],qf[4*ks+3], kh[6],kh[7]);
                }

                // ---- fused softmax (ex2) + PV over the 32 k-rows ----
                #pragma unroll
                for (int kv2 = 0; kv2 < 2; kv2++) {
                    const int kv = 2*half + kv2;
                    uint32_t ph[4];
                    #pragma unroll
                    for (int q = 0; q < 2; q++) {
                        int nf = 2*kv2 + q;
                        float p00, p01, p10, p11;
                        if (wfull) {
                            p00 = ex2f(Sa[nf][0]); p01 = ex2f(Sa[nf][1]);
                            p10 = ex2f(Sa[nf][2]); p11 = ex2f(Sa[nf][3]);
                        } else {
                            int kc = kbase + 16*kv + 8*q + 2*(l & 3);
                            p00 = (kc     <= grow0    ) ? ex2f(Sa[nf][0]) : 0.f;
                            p01 = (kc + 1 <= grow0    ) ? ex2f(Sa[nf][1]) : 0.f;
                            p10 = (kc     <= grow0 + 8) ? ex2f(Sa[nf][2]) : 0.f;
                            p11 = (kc + 1 <= grow0 + 8) ? ex2f(Sa[nf][3]) : 0.f;
                        }
                        lsum0 += p00 + p01;
                        lsum1 += p10 + p11;
                        ph[2*q]   = pack2h(p00, p01);
                        ph[2*q+1] = pack2h(p10, p11);
                    }
                    #pragma unroll
                    for (int q4 = 0; q4 < 4; q4++) {
                        uint32_t vh[8];
                        #pragma unroll
                        for (int pp = 0; pp < 2; pp++) {
                            int p2 = 2*q4 + pp;
                            uint32_t va = sVH + (uint32_t)((16*kv + (l & 15)) << 8)
                                              + (uint32_t)(((2*p2 + (l>>4)) ^ aswz) << 4);
                            LDSM_X4T(vh[4*pp],vh[4*pp+1],vh[4*pp+2],vh[4*pp+3], va);
                        }
                        MMA(Oa[4*q4],   ph[0],ph[1],ph[2],ph[3], vh[0],vh[1]);
                        MMA(Oa[4*q4+1], ph[0],ph[1],ph[2],ph[3], vh[2],vh[3]);
                        MMA(Oa[4*q4+2], ph[0],ph[1],ph[2],ph[3], vh[4],vh[5]);
                        MMA(Oa[4*q4+3], ph[0],ph[1],ph[2],ph[3], vh[6],vh[7]);
                    }
                }
            }
        }

        // ---- single barrier per ktile: wait for tile kt+1 loads, make them
        //      visible, AND confirm all warps finished reading stage kt&1 ----
        CP_WAIT0();                  // loads for tile kt+1 (issued one phase ago) done
        __syncthreads();             // visibility + readers-done-with stage (kt&1)
        if (kt + 2 < ntk) { load_kv(kt & 1, kt + 2); CP_COMMIT(); }
    }

    // ---- epilogue ----
    lsum0 += __shfl_xor_sync(0xffffffffu, lsum0, 1);
    lsum0 += __shfl_xor_sync(0xffffffffu, lsum0, 2);
    lsum1 += __shfl_xor_sync(0xffffffffu, lsum1, 1);
    lsum1 += __shfl_xor_sync(0xffffffffu, lsum1, 2);
    const float inv0 = 1.0f / lsum0, inv1 = 1.0f / lsum1;

    float* O0 = Og + ((size_t)bh * S_LEN + grow0) * DH;
    float* O1 = O0 + 8 * DH;
    #pragma unroll
    for (int nn2 = 0; nn2 < 16; nn2++) {
        int col = 8 * nn2 + 2 * (l & 3);
        *(float2*)(O0 + col) = make_float2(Oa[nn2][0] * inv0, Oa[nn2][1] * inv0);
        *(float2*)(O1 + col) = make_float2(Oa[nn2][2] * inv1, Oa[nn2][3] * inv1);
    }
}

extern "C" void kernel_launch(void* const* d_in, const int* in_sizes, int n_in,
                              void* d_out, int out_size)
{
    const float* K = (const float*)d_in[0];
    const float* V = (const float*)d_in[1];
    const float* Q = (const float*)d_in[2];
    float* O = (float*)d_out;

    split_prep<<<(int)(QUADS / 256), 256>>>(K, V);

    cudaFuncSetAttribute(fa_mma_kernel,
                         cudaFuncAttributeMaxDynamicSharedMemorySize, SM_TOTAL);
    dim3 grid(S_LEN / QT_ROWS, BH);   // (32 q-tiles, 64 batch*heads)
    fa_mma_kernel<<<grid, NT, SM_TOTAL>>>(Q, O);
}

// round 17
// speedup vs baseline: 1.1283x; 1.1283x over previous
#include <cuda_runtime.h>
#include <cuda_fp16.h>
#include <stdint.h>

#define S_LEN 2048
#define DH    128
#define BH    64
#define NT    128            // 4 warps; 3 CTAs co-resident per SM
#define QT_ROWS 64
#define KT_ROWS 64

#define ELEMS ((size_t)BH * S_LEN * DH)
#define QUADS (ELEMS / 4)

__device__ __align__(16) __half g_kh[ELEMS];
__device__ __align__(16) __half g_vh[ELEMS];

// SMEM: two 32KB stages {Kh,Vh}; Q staged through stage0 in the prologue
#define STAGE_B 32768u
#define OFF_VH  16384u
#define SM_TOTAL 65536

// scale * log2(e): exp(s) = ex2(q'.k) with q' = q * scale * log2e
#define SCALE_L2E 0.12751791802533652f

__device__ __forceinline__ uint32_t pack2h(float x, float y) {
    __half2 h = __floats2half2_rn(x, y);
    return *(uint32_t*)&h;
}
__device__ __forceinline__ float ex2f(float x) {
    float y;
    asm("ex2.approx.f32 %0, %1;" : "=f"(y) : "f"(x));
    return y;
}

__global__ void split_prep(const float* __restrict__ K, const float* __restrict__ V)
{
    const float4* k4 = (const float4*)K;
    const float4* v4 = (const float4*)V;
    uint2* kh = (uint2*)g_kh;
    uint2* vh = (uint2*)g_vh;
    size_t i = (size_t)blockIdx.x * blockDim.x + threadIdx.x;   // exact fit, no loop
    if (i < QUADS) {
        float4 k = k4[i];
        kh[i] = make_uint2(pack2h(k.x, k.y), pack2h(k.z, k.w));
        float4 v = v4[i];
        vh[i] = make_uint2(pack2h(v.x, v.y), pack2h(v.z, v.w));
    }
}

__device__ __forceinline__ uint32_t smem_u32(const void* p) {
    uint32_t a;
    asm("{ .reg .u64 t; cvta.to.shared.u64 t, %1; cvt.u32.u64 %0, t; }" : "=r"(a) : "l"(p));
    return a;
}
__device__ __forceinline__ void cpa16(uint32_t dst, const void* src) {
    asm volatile("cp.async.cg.shared.global [%0], [%1], 16;" :: "r"(dst), "l"(src));
}
#define CP_COMMIT() asm volatile("cp.async.commit_group;" ::: "memory")
#define CP_WAIT1()  asm volatile("cp.async.wait_group 1;" ::: "memory")

#define LDSM_X4(r0,r1,r2,r3,a) \
    asm volatile("ldmatrix.sync.aligned.m8n8.x4.shared.b16 {%0,%1,%2,%3},[%4];" \
                 : "=r"(r0),"=r"(r1),"=r"(r2),"=r"(r3) : "r"(a))
#define LDSM_X4T(r0,r1,r2,r3,a) \
    asm volatile("ldmatrix.sync.aligned.m8n8.x4.trans.shared.b16 {%0,%1,%2,%3},[%4];" \
                 : "=r"(r0),"=r"(r1),"=r"(r2),"=r"(r3) : "r"(a))
#define MMA(c,a0,a1,a2,a3,b0,b1) \
    asm volatile("mma.sync.aligned.m16n8k16.row.col.f32.f16.f16.f32 " \
                 "{%0,%1,%2,%3},{%4,%5,%6,%7},{%8,%9},{%0,%1,%2,%3};" \
                 : "+f"((c)[0]),"+f"((c)[1]),"+f"((c)[2]),"+f"((c)[3]) \
                 : "r"(a0),"r"(a1),"r"(a2),"r"(a3),"r"(b0),"r"(b1))

__global__ __launch_bounds__(NT, 3)
void fa_mma_kernel(const float* __restrict__ Qg_all, float* __restrict__ Og)
{
    extern __shared__ __align__(16) char sm8[];
    const uint32_t smb = smem_u32(sm8);
    const int tid = threadIdx.x;
    const int w = tid >> 5, l = tid & 31;

    // global LPT order: all heaviest q-tiles (across every bh) launch first
    const int qt = (int)gridDim.y - 1 - (int)blockIdx.y;
    const int bh = blockIdx.x;
    const size_t gbase = (size_t)bh * S_LEN * DH;
    const int ntk = qt + 1;

    const int aswz = l & 7;
    const int ainc = l >> 4;

    // ---- Q prologue: convert into stage0 smem, ldmatrix to persistent regs ----
    uint32_t qf[32];                 // 8 ks-steps x 4 regs; Q pre-scaled by scale*log2e
    {
        const float4* q4 = (const float4*)(Qg_all + gbase + (size_t)qt * QT_ROWS * DH);
        #pragma unroll
        for (int i = 0; i < 8; i++) {
            int it  = tid + i * NT;          // 64 rows x 16 chunks
            int row = it >> 4, ch = it & 15;
            float4 f0 = q4[row * 32 + ch * 2];
            float4 f1 = q4[row * 32 + ch * 2 + 1];
            uint4 hq = make_uint4(pack2h(f0.x*SCALE_L2E, f0.y*SCALE_L2E),
                                  pack2h(f0.z*SCALE_L2E, f0.w*SCALE_L2E),
                                  pack2h(f1.x*SCALE_L2E, f1.y*SCALE_L2E),
                                  pack2h(f1.z*SCALE_L2E, f1.w*SCALE_L2E));
            *(uint4*)(sm8 + (row << 8) + ((ch ^ (row & 7)) << 4)) = hq;
        }
        __syncthreads();
        const uint32_t qrowaddr = smb + (uint32_t)((16 * w + (l & 15)) << 8);
        #pragma unroll
        for (int ks = 0; ks < 8; ks++) {
            uint32_t qa = qrowaddr + (uint32_t)(((2*ks + ainc) ^ aswz) << 4);
            LDSM_X4(qf[4*ks], qf[4*ks+1], qf[4*ks+2], qf[4*ks+3], qa);
        }
        __syncthreads();             // stage0 free for K/V
    }

    auto load_kv = [&](int buf, int kti) {
        const uint32_t st = smb + (uint32_t)buf * STAGE_B;
        const size_t gb = gbase + (size_t)kti * KT_ROWS * DH;
        #pragma unroll
        for (int i = 0; i < 16; i++) {
            int it  = tid + i * NT;          // 2 arrays x 64 rows x 16 chunks
            int arr = it >> 10;
            int row = (it >> 4) & 63;
            int ch  = it & 15;
            uint32_t dst = st + (uint32_t)arr * 16384u + (row << 8) + ((ch ^ (row & 7)) << 4);
            const __half* sp = (arr == 0) ? g_kh : g_vh;
            cpa16(dst, sp + gb + (size_t)row * DH + ch * 8);
        }
    };
    load_kv(0, 0);
    CP_COMMIT();
    if (ntk > 1) { load_kv(1, 1); }
    CP_COMMIT();

    float Oa[16][4];
    #pragma unroll
    for (int i = 0; i < 16; i++) { Oa[i][0]=Oa[i][1]=Oa[i][2]=Oa[i][3]=0.f; }
    float lsum0 = 0.f, lsum1 = 0.f;

    const int grow0  = qt * QT_ROWS + 16 * w + (l >> 2);
    const int rowmax = qt * QT_ROWS + 16 * w + 15;

    for (int kt = 0; kt < ntk; kt++) {
        CP_WAIT1();                  // stage (kt&1) for tile kt resident
        __syncthreads();             // cp.async visibility across warps
        const int kbase = kt * KT_ROWS;

        if (kbase <= rowmax) {       // skip fully-masked warps on the diagonal tile
            const uint32_t st  = smb + (uint32_t)(kt & 1) * STAGE_B;
            const uint32_t sKH = st, sVH = st + OFF_VH;
            const bool wfull = (kbase + KT_ROWS - 1) <= (qt * QT_ROWS + 16 * w);

            #pragma unroll
            for (int half = 0; half < 2; half++) {
                if (kbase + 32 * half > rowmax) break;   // skip masked half-tiles

                // ---- S' = Q' @ K^T over 32 k-cols (log2-domain) ----
                float Sa[4][4];
                #pragma unroll
                for (int i = 0; i < 4; i++) { Sa[i][0]=Sa[i][1]=Sa[i][2]=Sa[i][3]=0.f; }

                #pragma unroll
                for (int ks = 0; ks < 8; ks++) {
                    uint32_t kh[8];
                    #pragma unroll
                    for (int pp = 0; pp < 2; pp++) {
                        int p = 2*half + pp;
                        uint32_t ka = sKH + (uint32_t)((8*(2*p + (l>>4)) + (l & 7)) << 8)
                                          + (uint32_t)(((2*ks + ((l>>3)&1)) ^ aswz) << 4);
                        LDSM_X4(kh[4*pp],kh[4*pp+1],kh[4*pp+2],kh[4*pp+3], ka);
                    }
                    MMA(Sa[0], qf[4*ks],qf[4*ks+1],qf[4*ks+2],qf[4*ks+3], kh[0],kh[1]);
                    MMA(Sa[1], qf[4*ks],qf[4*ks+1],qf[4*ks+2],qf[4*ks+3], kh[2],kh[3]);
                    MMA(Sa[2], qf[4*ks],qf[4*ks+1],qf[4*ks+2],qf[4*ks+3], kh[4],kh[5]);
                    MMA(Sa[3], qf[4*ks],qf[4*ks+1],qf[4*ks+2],qf[4*ks+3], kh[6],kh[7]);
                }

                // ---- fused softmax (ex2) + PV over the 32 k-rows ----
                #pragma unroll
                for (int kv2 = 0; kv2 < 2; kv2++) {
                    const int kv = 2*half + kv2;
                    uint32_t ph[4];
                    #pragma unroll
                    for (int q = 0; q < 2; q++) {
                        int nf = 2*kv2 + q;
                        float p00, p01, p10, p11;
                        if (wfull) {
                            p00 = ex2f(Sa[nf][0]); p01 = ex2f(Sa[nf][1]);
                            p10 = ex2f(Sa[nf][2]); p11 = ex2f(Sa[nf][3]);
                        } else {
                            int kc = kbase + 16*kv + 8*q + 2*(l & 3);
                            p00 = (kc     <= grow0    ) ? ex2f(Sa[nf][0]) : 0.f;
                            p01 = (kc + 1 <= grow0    ) ? ex2f(Sa[nf][1]) : 0.f;
                            p10 = (kc     <= grow0 + 8) ? ex2f(Sa[nf][2]) : 0.f;
                            p11 = (kc + 1 <= grow0 + 8) ? ex2f(Sa[nf][3]) : 0.f;
                        }
                        lsum0 += p00 + p01;
                        lsum1 += p10 + p11;
                        ph[2*q]   = pack2h(p00, p01);
                        ph[2*q+1] = pack2h(p10, p11);
                    }
                    #pragma unroll
                    for (int q4 = 0; q4 < 4; q4++) {
                        uint32_t vh[8];
                        #pragma unroll
                        for (int pp = 0; pp < 2; pp++) {
                            int p2 = 2*q4 + pp;
                            uint32_t va = sVH + (uint32_t)((16*kv + (l & 15)) << 8)
                                              + (uint32_t)(((2*p2 + (l>>4)) ^ aswz) << 4);
                            LDSM_X4T(vh[4*pp],vh[4*pp+1],vh[4*pp+2],vh[4*pp+3], va);
                        }
                        MMA(Oa[4*q4],   ph[0],ph[1],ph[2],ph[3], vh[0],vh[1]);
                        MMA(Oa[4*q4+1], ph[0],ph[1],ph[2],ph[3], vh[2],vh[3]);
                        MMA(Oa[4*q4+2], ph[0],ph[1],ph[2],ph[3], vh[4],vh[5]);
                        MMA(Oa[4*q4+3], ph[0],ph[1],ph[2],ph[3], vh[6],vh[7]);
                    }
                }
            }
        }

        __syncthreads();             // all warps done reading stage (kt&1)
        if (kt + 2 < ntk) load_kv(kt & 1, kt + 2);
        CP_COMMIT();
    }

    // ---- epilogue ----
    lsum0 += __shfl_xor_sync(0xffffffffu, lsum0, 1);
    lsum0 += __shfl_xor_sync(0xffffffffu, lsum0, 2);
    lsum1 += __shfl_xor_sync(0xffffffffu, lsum1, 1);
    lsum1 += __shfl_xor_sync(0xffffffffu, lsum1, 2);
    const float inv0 = 1.0f / lsum0, inv1 = 1.0f / lsum1;

    float* O0 = Og + ((size_t)bh * S_LEN + grow0) * DH;
    float* O1 = O0 + 8 * DH;
    #pragma unroll
    for (int nn2 = 0; nn2 < 16; nn2++) {
        int col = 8 * nn2 + 2 * (l & 3);
        *(float2*)(O0 + col) = make_float2(Oa[nn2][0] * inv0, Oa[nn2][1] * inv0);
        *(float2*)(O1 + col) = make_float2(Oa[nn2][2] * inv1, Oa[nn2][3] * inv1);
    }
}

extern "C" void kernel_launch(void* const* d_in, const int* in_sizes, int n_in,
                              void* d_out, int out_size)
{
    const float* K = (const float*)d_in[0];
    const float* V = (const float*)d_in[1];
    const float* Q = (const float*)d_in[2];
    float* O = (float*)d_out;

    split_prep<<<(int)(QUADS / 256), 256>>>(K, V);

    cudaFuncSetAttribute(fa_mma_kernel,
                         cudaFuncAttributeMaxDynamicSharedMemorySize, SM_TOTAL);
    dim3 grid(BH, S_LEN / QT_ROWS);   // (64 bh, 32 qt) -> global LPT launch order
    fa_mma_kernel<<<grid, NT, SM_TOTAL>>>(Q, O);
}